// round 14
// baseline (speedup 1.0000x reference)
#include <cuda_runtime.h>
#include <cuda_bf16.h>
#include <cuda_fp16.h>
#include <math.h>
#include <stdint.h>

#define BATCH  8
#define SEQ    4096
#define DIM    1024
#define SDIM   64
#define SHIFTN 2048
#define MTOT   (BATCH*SEQ)   /* 32768 */
#define CH     128
#define NCH    (SEQ/CH)      /* 32 */

/* fp16 GEMMs: CTA 128x128, stage = A 16K + B 16K = 32K, 3 stages, 2 CTA/SM */
#define G_B     16384
#define G_STAGE 32768
#define G_NST   3

/* out GEMM: CTA 128x256, single stage = A 16K + B 32K */
#define O_B     16384

// ---------------------------------------------------------------------------
// Device scratch
// ---------------------------------------------------------------------------
__device__ __align__(16) __half g_xsf[(size_t)MTOT * DIM];    /* blended x_shift, fp16 */
__device__ __align__(16) __half g_xf[(size_t)MTOT * DIM];     /* x fp16 row-major */
__device__ __align__(16) __half g_Wshf[(size_t)DIM * DIM];    /* W_shift fp16 */
__device__ __align__(16) __half g_xnf[(size_t)MTOT * DIM];    /* xn fp16 */
__device__ __align__(16) __half g_Wkvf[128 * DIM];            /* interleaved k/v fp16 */
__device__ __align__(16) __half g_Wof[DIM * SDIM];            /* W_output fp16 */
__device__ __align__(16) __half g_stf[(size_t)MTOT * SDIM];   /* states fp16 */
__device__ float g_wkv[(size_t)MTOT * SDIM];
__device__ float g_lasts[BATCH * NCH * SDIM];
__device__ float g_carry[BATCH * NCH * SDIM];

// ---------------------------------------------------------------------------
// PTX helpers (sm_80-level portable PTX only)
// ---------------------------------------------------------------------------
__device__ __forceinline__ uint32_t smem_u32(const void* p) {
    uint32_t a;
    asm("{ .reg .u64 t; cvta.to.shared.u64 t, %1; cvt.u32.u64 %0, t; }"
        : "=r"(a) : "l"(p));
    return a;
}
__device__ __forceinline__ void cp16(uint32_t d, const void* s) {
    asm volatile("cp.async.cg.shared.global [%0], [%1], 16;" :: "r"(d), "l"(s));
}
__device__ __forceinline__ void cp_commit() { asm volatile("cp.async.commit_group;"); }
__device__ __forceinline__ void cp_wait0()  { asm volatile("cp.async.wait_group 0;"); }
__device__ __forceinline__ void cp_wait1()  { asm volatile("cp.async.wait_group 1;"); }

__device__ __forceinline__ void ldsm4(uint32_t* r, uint32_t a) {
    asm volatile("ldmatrix.sync.aligned.m8n8.x4.shared.b16 {%0,%1,%2,%3}, [%4];"
                 : "=r"(r[0]), "=r"(r[1]), "=r"(r[2]), "=r"(r[3]) : "r"(a));
}
__device__ __forceinline__ void mma_fp(float* c, const uint32_t* a, const uint32_t* b) {
    asm volatile(
        "mma.sync.aligned.m16n8k16.row.col.f32.f16.f16.f32 "
        "{%0,%1,%2,%3}, {%4,%5,%6,%7}, {%8,%9}, {%0,%1,%2,%3};"
        : "+f"(c[0]), "+f"(c[1]), "+f"(c[2]), "+f"(c[3])
        : "r"(a[0]), "r"(a[1]), "r"(a[2]), "r"(a[3]), "r"(b[0]), "r"(b[1]));
}

// plain fp16 chunk: warp tile 64x32 (4m x 4n); A at base, B at +G_B
__device__ __forceinline__ void mma_stage_g(uint32_t base, int wm, int wn, int lane,
                                            float C[4][4][4])
{
    const int ra = lane & 15;
    const int ha = lane >> 4;
    const int gq = lane >> 3;
    const int rb = ((gq >> 1) * 8) + (lane & 7);
    const int hb = gq & 1;
#pragma unroll
    for (int s = 0; s < 4; s++) {
        uint32_t aa[4][4], bb[2][4];
        const int ca = 2 * s + ha;
        const int cb = 2 * s + hb;
#pragma unroll
        for (int i = 0; i < 4; i++) {
            int r = wm + i * 16 + ra;
            ldsm4(aa[i], base + r * 128 + ((ca ^ (r & 7)) << 4));
        }
#pragma unroll
        for (int p = 0; p < 2; p++) {
            int n = wn + p * 16 + rb;
            ldsm4(bb[p], base + G_B + n * 128 + ((cb ^ (n & 7)) << 4));
        }
#pragma unroll
        for (int i = 0; i < 4; i++)
#pragma unroll
            for (int j = 0; j < 4; j++) {
                const uint32_t* B = &bb[j >> 1][(j & 1) * 2];
                mma_fp(C[i][j], aa[i], B);
            }
    }
}

// out variant: warp tile 64x64 (4m x 8n); A at base, B at +O_B
__device__ __forceinline__ void mma_stage_o(uint32_t base, int wm, int wn, int lane,
                                            float C[4][8][4])
{
    const int ra = lane & 15;
    const int ha = lane >> 4;
    const int gq = lane >> 3;
    const int rb = ((gq >> 1) * 8) + (lane & 7);
    const int hb = gq & 1;
#pragma unroll
    for (int s = 0; s < 4; s++) {
        uint32_t aa[4][4], bb[4][4];
        const int ca = 2 * s + ha;
        const int cb = 2 * s + hb;
#pragma unroll
        for (int i = 0; i < 4; i++) {
            int r = wm + i * 16 + ra;
            ldsm4(aa[i], base + r * 128 + ((ca ^ (r & 7)) << 4));
        }
#pragma unroll
        for (int p = 0; p < 4; p++) {
            int n = wn + p * 16 + rb;
            ldsm4(bb[p], base + O_B + n * 128 + ((cb ^ (n & 7)) << 4));
        }
#pragma unroll
        for (int i = 0; i < 4; i++)
#pragma unroll
            for (int j = 0; j < 8; j++) {
                const uint32_t* B = &bb[j >> 1][(j & 1) * 2];
                mma_fp(C[i][j], aa[i], B);
            }
    }
}

// ---------------------------------------------------------------------------
// Unified prep kernel (fp32 -> fp16), block-range dispatch
// ---------------------------------------------------------------------------
union U8h { uint4 u; __half h[8]; };

__global__ void k_prep_all(const float* __restrict__ x, const float* __restrict__ Wsh,
                           const float* __restrict__ Wk, const float* __restrict__ Wv,
                           const float* __restrict__ Wo)
{
    int b = blockIdx.x;
    const float* src;
    __half* dst;
    size_t i;
    if (b < 16384) {
        i = ((size_t)b * 256 + threadIdx.x) * 8;
        src = x + i; dst = g_xf + i;
    } else if (b < 16896) {
        i = ((size_t)(b - 16384) * 256 + threadIdx.x) * 8;
        src = Wsh + i; dst = g_Wshf + i;
    } else if (b < 16960) {
        i = ((size_t)(b - 16896) * 256 + threadIdx.x) * 8;
        int row = (int)(i >> 10), col = (int)(i & 1023);
        src = ((row & 1) ? Wv : Wk) + (size_t)(row >> 1) * DIM + col;
        dst = g_Wkvf + i;
    } else {
        i = ((size_t)(b - 16960) * 256 + threadIdx.x) * 8;
        src = Wo + i; dst = g_Wof + i;
    }
    float f[8];
    *(float4*)(f)     = *(const float4*)(src);
    *(float4*)(f + 4) = *(const float4*)(src + 4);
    U8h H;
#pragma unroll
    for (int j = 0; j < 8; j++) H.h[j] = __float2half(f[j]);
    *(uint4*)dst = H.u;
}

// ---------------------------------------------------------------------------
// GEMM 1: g_xsf[m, e] = fp16( blend( x_cat @ W_shift^T, x ) )  -- blend fused
// plain fp16, CTA 128x128, 3-stage (prefetch distance 2), 2 CTA/SM
// ---------------------------------------------------------------------------
__global__ __launch_bounds__(256, 2)
void k_gemm_shift(const float* __restrict__ sg)
{
    extern __shared__ __align__(128) char smc[];
    const uint32_t sbase = smem_u32(smc);
    const int tid = threadIdx.x;
    const int warp = tid >> 5, lane = tid & 31;
    const int wm = (warp & 1) * 64, wn = (warp >> 1) * 32;
    const int m0 = blockIdx.y * 128, e0 = blockIdx.x * 128;

    const int grp = tid & 7;
    const __half *pA[4], *pB[4];
    uint32_t soff[4];
#pragma unroll
    for (int i = 0; i < 4; i++) {
        int r = (tid >> 3) + i * 32;
        int m = m0 + r;
        int b = m >> 12, t = m & 4095;
        int ts = (t + SHIFTN) & 4095;
        pA[i] = g_xf + ((size_t)((b << 12) + ts)) * DIM + grp * 8;
        pB[i] = g_Wshf + (size_t)(e0 + r) * DIM + grp * 8;
        soff[i] = r * 128 + ((grp ^ (r & 7)) << 4);
    }

    float C[4][4][4];
#pragma unroll
    for (int i = 0; i < 4; i++)
#pragma unroll
        for (int j = 0; j < 4; j++)
#pragma unroll
            for (int q = 0; q < 4; q++) C[i][j][q] = 0.f;

    // prologue: chunks 0,1 into stages 0,1
#pragma unroll
    for (int pc = 0; pc < 2; pc++) {
        uint32_t sb = sbase + pc * G_STAGE;
        int k0 = pc * 64;
#pragma unroll
        for (int i = 0; i < 4; i++) {
            cp16(sb + soff[i], pA[i] + k0);
            cp16(sb + G_B + soff[i], pB[i] + k0);
        }
        cp_commit();
    }

    const int NC = 16;
    int buf = 0;
    for (int c = 0; c < NC; c++) {
        if (c >= NC - 2) cp_wait0(); else cp_wait1();
        __syncthreads();
        if (c + 2 < NC) {
            int nb = buf + 2; if (nb >= G_NST) nb -= G_NST;
            uint32_t sb = sbase + nb * G_STAGE;
            int k0 = (c + 2) * 64;
#pragma unroll
            for (int i = 0; i < 4; i++) {
                cp16(sb + soff[i], pA[i] + k0);
                cp16(sb + G_B + soff[i], pB[i] + k0);
            }
            cp_commit();
        }
        mma_stage_g(sbase + buf * G_STAGE, wm, wn, lane, C);
        if (++buf == G_NST) buf = 0;
    }

    // epilogue: gated blend with x (fp16), write blended fp16
#pragma unroll
    for (int j = 0; j < 4; j++) {
        int col = e0 + wn + j * 8 + (lane & 3) * 2;
        float gv0 = sg[col], gv1 = sg[col + 1];
        float gt0 = 1.f / (1.f + expf(-gv0));
        float gt1 = 1.f / (1.f + expf(-gv1));
#pragma unroll
        for (int i = 0; i < 4; i++) {
            int r0 = m0 + wm + i * 16 + (lane >> 2);
            float2 x0 = __half22float2(*(const __half2*)&g_xf[(size_t)r0 * DIM + col]);
            float2 x1 = __half22float2(*(const __half2*)&g_xf[(size_t)(r0 + 8) * DIM + col]);
            __half2 h0 = __floats2half2_rn(C[i][j][0] * gt0 + x0.x * (1.f - gt0),
                                           C[i][j][1] * gt1 + x0.y * (1.f - gt1));
            __half2 h1 = __floats2half2_rn(C[i][j][2] * gt0 + x1.x * (1.f - gt0),
                                           C[i][j][3] * gt1 + x1.y * (1.f - gt1));
            *(__half2*)&g_xsf[(size_t)r0 * DIM + col]       = h0;
            *(__half2*)&g_xsf[(size_t)(r0 + 8) * DIM + col] = h1;
        }
    }
}

// ---------------------------------------------------------------------------
// layernorm (input already blended) -> fp16 xn
// ---------------------------------------------------------------------------
__inline__ __device__ float warp_sum(float v) {
#pragma unroll
    for (int o = 16; o > 0; o >>= 1) v += __shfl_xor_sync(0xffffffffu, v, o);
    return v;
}

union U4h { uint2 u; __half h[4]; __half2 h2[2]; };

__global__ __launch_bounds__(256)
void k_ln(const float* __restrict__ lnw, const float* __restrict__ lnb)
{
    int m = blockIdx.x;
    int tid = threadIdx.x;
    size_t off = (size_t)m * DIM + tid * 4;
    U4h xs;
    xs.u = *(const uint2*)(g_xsf + off);
    float2 s0 = __half22float2(xs.h2[0]), s1 = __half22float2(xs.h2[1]);
    float4 v = make_float4(s0.x, s0.y, s1.x, s1.y);

    float s  = v.x + v.y + v.z + v.w;
    float ss = fmaf(v.x, v.x, fmaf(v.y, v.y, fmaf(v.z, v.z, v.w * v.w)));
    s = warp_sum(s); ss = warp_sum(ss);
    __shared__ float sh_s[8], sh_ss[8];
    int wid = tid >> 5, lane = tid & 31;
    if (lane == 0) { sh_s[wid] = s; sh_ss[wid] = ss; }
    __syncthreads();
    if (wid == 0) {
        float a = (lane < 8) ? sh_s[lane] : 0.f;
        float b = (lane < 8) ? sh_ss[lane] : 0.f;
        a = warp_sum(a); b = warp_sum(b);
        if (lane == 0) { sh_s[0] = a; sh_ss[0] = b; }
    }
    __syncthreads();
    float mu  = sh_s[0] * (1.f / DIM);
    float var = sh_ss[0] * (1.f / DIM) - mu * mu;
    float rstd = rsqrtf(var + 1e-5f);
    float4 w4 = ((const float4*)lnw)[tid];
    float4 b4 = ((const float4*)lnb)[tid];
    U4h H;
    H.h[0] = __float2half((v.x - mu) * rstd * w4.x + b4.x);
    H.h[1] = __float2half((v.y - mu) * rstd * w4.y + b4.y);
    H.h[2] = __float2half((v.z - mu) * rstd * w4.z + b4.z);
    H.h[3] = __float2half((v.w - mu) * rstd * w4.w + b4.w);
    *(uint2*)(g_xnf + off) = H.u;
}

// ---------------------------------------------------------------------------
// GEMM 2: [k|v] interleaved = xn @ Wkv^T (plain fp16), fused wkv epilogue
// ---------------------------------------------------------------------------
__global__ __launch_bounds__(256, 2)
void k_gemm_kv(const float* __restrict__ time_first)
{
    extern __shared__ __align__(128) char smc[];
    const uint32_t sbase = smem_u32(smc);
    const int tid = threadIdx.x;
    const int warp = tid >> 5, lane = tid & 31;
    const int wm = (warp & 1) * 64, wn = (warp >> 1) * 32;
    const int m0 = blockIdx.y * 128;

    const int grp = tid & 7;
    const __half *pA[4], *pB[4];
    uint32_t soff[4];
#pragma unroll
    for (int i = 0; i < 4; i++) {
        int r = (tid >> 3) + i * 32;
        pA[i] = g_xnf + (size_t)(m0 + r) * DIM + grp * 8;
        pB[i] = g_Wkvf + (size_t)r * DIM + grp * 8;
        soff[i] = r * 128 + ((grp ^ (r & 7)) << 4);
    }

    float C[4][4][4];
#pragma unroll
    for (int i = 0; i < 4; i++)
#pragma unroll
        for (int j = 0; j < 4; j++)
#pragma unroll
            for (int q = 0; q < 4; q++) C[i][j][q] = 0.f;

#pragma unroll
    for (int pc = 0; pc < 2; pc++) {
        uint32_t sb = sbase + pc * G_STAGE;
        int k0 = pc * 64;
#pragma unroll
        for (int i = 0; i < 4; i++) {
            cp16(sb + soff[i], pA[i] + k0);
            cp16(sb + G_B + soff[i], pB[i] + k0);
        }
        cp_commit();
    }

    const int NC = 16;
    int buf = 0;
    for (int c = 0; c < NC; c++) {
        if (c >= NC - 2) cp_wait0(); else cp_wait1();
        __syncthreads();
        if (c + 2 < NC) {
            int nb = buf + 2; if (nb >= G_NST) nb -= G_NST;
            uint32_t sb = sbase + nb * G_STAGE;
            int k0 = (c + 2) * 64;
#pragma unroll
            for (int i = 0; i < 4; i++) {
                cp16(sb + soff[i], pA[i] + k0);
                cp16(sb + G_B + soff[i], pB[i] + k0);
            }
            cp_commit();
        }
        mma_stage_g(sbase + buf * G_STAGE, wm, wn, lane, C);
        if (++buf == G_NST) buf = 0;
    }

    // C cols: even = k_s, odd = v_s
#pragma unroll
    for (int i = 0; i < 4; i++)
#pragma unroll
        for (int j = 0; j < 4; j++) {
            int r0 = m0 + wm + i * 16 + (lane >> 2);
            int sidx = (wn >> 1) + j * 4 + (lane & 3);
            float ex = expf(time_first[sidx]);
            float k0v = C[i][j][0], v0v = C[i][j][1];
            float k1v = C[i][j][2], v1v = C[i][j][3];
            float w0 = expf(-ex * (1.f / (1.f + expf(-k0v)))) * v0v;
            float w1 = expf(-ex * (1.f / (1.f + expf(-k1v)))) * v1v;
            g_wkv[(size_t)r0 * SDIM + sidx]       = w0;
            g_wkv[(size_t)(r0 + 8) * SDIM + sidx] = w1;
        }
}

// ---------------------------------------------------------------------------
// Recurrence (chunked scan, CH=128)
// ---------------------------------------------------------------------------
__global__ void k_rec_lasts(const float* __restrict__ td)
{
    int ch = blockIdx.x, b = blockIdx.y, s = threadIdx.x;
    float w = expf(td[s]);
    const float* wp = g_wkv + ((size_t)(b * SEQ + ch * CH)) * SDIM + s;
    float st = 0.f;
#pragma unroll 8
    for (int t = 0; t < CH; t++) st = fmaf(st, w, wp[(size_t)t * SDIM]);
    g_lasts[(b * NCH + ch) * SDIM + s] = st;
}

__global__ void k_rec_carry(const float* __restrict__ td, float* __restrict__ last_out)
{
    int b = blockIdx.x, s = threadIdx.x;
    float wC = expf((float)CH * td[s]);
    float st = 0.f;
    for (int c = 0; c < NCH; c++) {
        g_carry[(b * NCH + c) * SDIM + s] = st;
        st = st * wC + g_lasts[(b * NCH + c) * SDIM + s];
    }
    last_out[b * SDIM + s] = st;
}

__global__ void k_rec_scan(const float* __restrict__ td)
{
    int ch = blockIdx.x, b = blockIdx.y, s = threadIdx.x;
    float w = expf(td[s]);
    float st = g_carry[(b * NCH + ch) * SDIM + s];
    size_t m0 = (size_t)(b * SEQ + ch * CH);
    const float* wp = g_wkv + m0 * SDIM + s;
#pragma unroll 8
    for (int t = 0; t < CH; t++) {
        st = fmaf(st, w, wp[(size_t)t * SDIM]);
        g_stf[(m0 + t) * SDIM + s] = __float2half(st);
    }
}

// ---------------------------------------------------------------------------
// GEMM 3: out = states @ Wo^T  (plain fp16, K = 64, CTA 128x256)
// ---------------------------------------------------------------------------
__global__ __launch_bounds__(256)
void k_gemm_out(float* __restrict__ out)
{
    extern __shared__ __align__(128) char smc[];
    const uint32_t sbase = smem_u32(smc);
    const int tid = threadIdx.x;
    const int warp = tid >> 5, lane = tid & 31;
    const int wm = (warp & 1) * 64, wn = (warp >> 1) * 64;
    const int m0 = blockIdx.y * 128, d0 = blockIdx.x * 256;

    const int grp = tid & 7;
#pragma unroll
    for (int i = 0; i < 4; i++) {
        int r = (tid >> 3) + i * 32;
        uint32_t so = r * 128 + ((grp ^ (r & 7)) << 4);
        cp16(sbase + so, g_stf + (size_t)(m0 + r) * SDIM + grp * 8);
    }
#pragma unroll
    for (int i = 0; i < 8; i++) {
        int r = (tid >> 3) + i * 32;     /* 0..255 */
        uint32_t so = r * 128 + ((grp ^ (r & 7)) << 4);
        cp16(sbase + O_B + so, g_Wof + (size_t)(d0 + r) * SDIM + grp * 8);
    }
    cp_commit();

    float C[4][8][4];
#pragma unroll
    for (int i = 0; i < 4; i++)
#pragma unroll
        for (int j = 0; j < 8; j++)
#pragma unroll
            for (int q = 0; q < 4; q++) C[i][j][q] = 0.f;

    cp_wait0();
    __syncthreads();
    mma_stage_o(sbase, wm, wn, lane, C);

#pragma unroll
    for (int i = 0; i < 4; i++)
#pragma unroll
        for (int j = 0; j < 8; j++) {
            int r0 = m0 + wm + i * 16 + (lane >> 2);
            int col = d0 + wn + j * 8 + (lane & 3) * 2;
            *(float2*)&out[(size_t)r0 * DIM + col] =
                make_float2(C[i][j][0], C[i][j][1]);
            *(float2*)&out[(size_t)(r0 + 8) * DIM + col] =
                make_float2(C[i][j][2], C[i][j][3]);
        }
}

// ---------------------------------------------------------------------------
extern "C" void kernel_launch(void* const* d_in, const int* in_sizes, int n_in,
                              void* d_out, int out_size)
{
    const float* x   = (const float*)d_in[0];
    const float* td  = (const float*)d_in[1];
    const float* tf  = (const float*)d_in[2];
    const float* Wk  = (const float*)d_in[3];
    const float* Wv  = (const float*)d_in[4];
    const float* Wo  = (const float*)d_in[5];
    const float* Wsh = (const float*)d_in[6];
    const float* sg  = (const float*)d_in[7];
    const float* lnw = (const float*)d_in[8];
    const float* lnb = (const float*)d_in[9];

    float* out  = (float*)d_out;
    float* last = out + (size_t)MTOT * DIM;

    const int SMEM_G = G_NST * G_STAGE;   // 98304 -> 2 CTA/SM
    const int SMEM_O = 49152;             // A 16K + B 32K
    cudaFuncSetAttribute(k_gemm_shift, cudaFuncAttributeMaxDynamicSharedMemorySize, SMEM_G);
    cudaFuncSetAttribute(k_gemm_kv,    cudaFuncAttributeMaxDynamicSharedMemorySize, SMEM_G);
    cudaFuncSetAttribute(k_gemm_out,   cudaFuncAttributeMaxDynamicSharedMemorySize, SMEM_O);

    k_prep_all<<<16992, 256>>>(x, Wsh, Wk, Wv, Wo);
    k_gemm_shift<<<dim3(DIM / 128, MTOT / 128), 256, SMEM_G>>>(sg);
    k_ln<<<MTOT, 256>>>(lnw, lnb);
    k_gemm_kv<<<dim3(1, MTOT / 128), 256, SMEM_G>>>(tf);   // launch index 3 -> profiled

    k_rec_lasts<<<dim3(NCH, BATCH), SDIM>>>(td);
    k_rec_carry<<<BATCH, SDIM>>>(td, last);
    k_rec_scan <<<dim3(NCH, BATCH), SDIM>>>(td);

    k_gemm_out<<<dim3(DIM / 256, MTOT / 128), 256, SMEM_O>>>(out);
}

// round 15
// speedup vs baseline: 1.0087x; 1.0087x over previous
#include <cuda_runtime.h>
#include <cuda_bf16.h>
#include <cuda_fp16.h>
#include <math.h>
#include <stdint.h>

#define BATCH  8
#define SEQ    4096
#define DIM    1024
#define SDIM   64
#define SHIFTN 2048
#define MTOT   (BATCH*SEQ)   /* 32768 */
#define CH     128
#define NCH    (SEQ/CH)      /* 32 */

/* fp16 GEMMs: CTA 128x128, stage = A 16K + B 16K = 32K, 3 stages, 2 CTA/SM */
#define G_B     16384
#define G_STAGE 32768
#define G_NST   3

/* out GEMM: CTA 128x256, single stage = A 16K + B 32K */
#define O_B     16384

// ---------------------------------------------------------------------------
// Device scratch
// ---------------------------------------------------------------------------
__device__ __align__(16) __half g_xsf[(size_t)MTOT * DIM];    /* shift-GEMM out, fp16 */
__device__ __align__(16) __half g_xf[(size_t)MTOT * DIM];     /* x fp16 row-major */
__device__ __align__(16) __half g_Wshf[(size_t)DIM * DIM];    /* W_shift fp16 */
__device__ __align__(16) __half g_xnf[(size_t)MTOT * DIM];    /* xn fp16 */
__device__ __align__(16) __half g_Wkvf[128 * DIM];            /* interleaved k/v fp16 */
__device__ __align__(16) __half g_Wof[DIM * SDIM];            /* W_output fp16 */
__device__ __align__(16) __half g_stf[(size_t)MTOT * SDIM];   /* states fp16 */
__device__ float g_wkv[(size_t)MTOT * SDIM];
__device__ float g_lasts[BATCH * NCH * SDIM];
__device__ float g_carry[BATCH * NCH * SDIM];

// ---------------------------------------------------------------------------
// PTX helpers (sm_80-level portable PTX only)
// ---------------------------------------------------------------------------
__device__ __forceinline__ uint32_t smem_u32(const void* p) {
    uint32_t a;
    asm("{ .reg .u64 t; cvta.to.shared.u64 t, %1; cvt.u32.u64 %0, t; }"
        : "=r"(a) : "l"(p));
    return a;
}
__device__ __forceinline__ void cp16(uint32_t d, const void* s) {
    asm volatile("cp.async.cg.shared.global [%0], [%1], 16;" :: "r"(d), "l"(s));
}
__device__ __forceinline__ void cp_commit() { asm volatile("cp.async.commit_group;"); }
__device__ __forceinline__ void cp_wait0()  { asm volatile("cp.async.wait_group 0;"); }
__device__ __forceinline__ void cp_wait1()  { asm volatile("cp.async.wait_group 1;"); }

__device__ __forceinline__ void ldsm4(uint32_t* r, uint32_t a) {
    asm volatile("ldmatrix.sync.aligned.m8n8.x4.shared.b16 {%0,%1,%2,%3}, [%4];"
                 : "=r"(r[0]), "=r"(r[1]), "=r"(r[2]), "=r"(r[3]) : "r"(a));
}
__device__ __forceinline__ void mma_fp(float* c, const uint32_t* a, const uint32_t* b) {
    asm volatile(
        "mma.sync.aligned.m16n8k16.row.col.f32.f16.f16.f32 "
        "{%0,%1,%2,%3}, {%4,%5,%6,%7}, {%8,%9}, {%0,%1,%2,%3};"
        : "+f"(c[0]), "+f"(c[1]), "+f"(c[2]), "+f"(c[3])
        : "r"(a[0]), "r"(a[1]), "r"(a[2]), "r"(a[3]), "r"(b[0]), "r"(b[1]));
}

// plain fp16 chunk: warp tile 64x32 (4m x 4n); A at base, B at +G_B
__device__ __forceinline__ void mma_stage_g(uint32_t base, int wm, int wn, int lane,
                                            float C[4][4][4])
{
    const int ra = lane & 15;
    const int ha = lane >> 4;
    const int gq = lane >> 3;
    const int rb = ((gq >> 1) * 8) + (lane & 7);
    const int hb = gq & 1;
#pragma unroll
    for (int s = 0; s < 4; s++) {
        uint32_t aa[4][4], bb[2][4];
        const int ca = 2 * s + ha;
        const int cb = 2 * s + hb;
#pragma unroll
        for (int i = 0; i < 4; i++) {
            int r = wm + i * 16 + ra;
            ldsm4(aa[i], base + r * 128 + ((ca ^ (r & 7)) << 4));
        }
#pragma unroll
        for (int p = 0; p < 2; p++) {
            int n = wn + p * 16 + rb;
            ldsm4(bb[p], base + G_B + n * 128 + ((cb ^ (n & 7)) << 4));
        }
#pragma unroll
        for (int i = 0; i < 4; i++)
#pragma unroll
            for (int j = 0; j < 4; j++) {
                const uint32_t* B = &bb[j >> 1][(j & 1) * 2];
                mma_fp(C[i][j], aa[i], B);
            }
    }
}

// out variant: warp tile 64x64 (4m x 8n); A at base, B at +O_B
__device__ __forceinline__ void mma_stage_o(uint32_t base, int wm, int wn, int lane,
                                            float C[4][8][4])
{
    const int ra = lane & 15;
    const int ha = lane >> 4;
    const int gq = lane >> 3;
    const int rb = ((gq >> 1) * 8) + (lane & 7);
    const int hb = gq & 1;
#pragma unroll
    for (int s = 0; s < 4; s++) {
        uint32_t aa[4][4], bb[4][4];
        const int ca = 2 * s + ha;
        const int cb = 2 * s + hb;
#pragma unroll
        for (int i = 0; i < 4; i++) {
            int r = wm + i * 16 + ra;
            ldsm4(aa[i], base + r * 128 + ((ca ^ (r & 7)) << 4));
        }
#pragma unroll
        for (int p = 0; p < 4; p++) {
            int n = wn + p * 16 + rb;
            ldsm4(bb[p], base + O_B + n * 128 + ((cb ^ (n & 7)) << 4));
        }
#pragma unroll
        for (int i = 0; i < 4; i++)
#pragma unroll
            for (int j = 0; j < 8; j++) {
                const uint32_t* B = &bb[j >> 1][(j & 1) * 2];
                mma_fp(C[i][j], aa[i], B);
            }
    }
}

// ---------------------------------------------------------------------------
// Unified prep kernel (fp32 -> fp16), block-range dispatch
// ---------------------------------------------------------------------------
union U8h { uint4 u; __half h[8]; };

__global__ void k_prep_all(const float* __restrict__ x, const float* __restrict__ Wsh,
                           const float* __restrict__ Wk, const float* __restrict__ Wv,
                           const float* __restrict__ Wo)
{
    int b = blockIdx.x;
    const float* src;
    __half* dst;
    size_t i;
    if (b < 16384) {
        i = ((size_t)b * 256 + threadIdx.x) * 8;
        src = x + i; dst = g_xf + i;
    } else if (b < 16896) {
        i = ((size_t)(b - 16384) * 256 + threadIdx.x) * 8;
        src = Wsh + i; dst = g_Wshf + i;
    } else if (b < 16960) {
        i = ((size_t)(b - 16896) * 256 + threadIdx.x) * 8;
        int row = (int)(i >> 10), col = (int)(i & 1023);
        src = ((row & 1) ? Wv : Wk) + (size_t)(row >> 1) * DIM + col;
        dst = g_Wkvf + i;
    } else {
        i = ((size_t)(b - 16960) * 256 + threadIdx.x) * 8;
        src = Wo + i; dst = g_Wof + i;
    }
    float f[8];
    *(float4*)(f)     = *(const float4*)(src);
    *(float4*)(f + 4) = *(const float4*)(src + 4);
    U8h H;
#pragma unroll
    for (int j = 0; j < 8; j++) H.h[j] = __float2half(f[j]);
    *(uint4*)dst = H.u;
}

// ---------------------------------------------------------------------------
// GEMM 1: g_xsf[m, e] = fp16( x_cat[m, :] @ W_shift[e, :] )
// plain fp16, CTA 128x128, 3-stage (prefetch distance 2), 2 CTA/SM
// ---------------------------------------------------------------------------
__global__ __launch_bounds__(256, 2)
void k_gemm_shift()
{
    extern __shared__ __align__(128) char smc[];
    const uint32_t sbase = smem_u32(smc);
    const int tid = threadIdx.x;
    const int warp = tid >> 5, lane = tid & 31;
    const int wm = (warp & 1) * 64, wn = (warp >> 1) * 32;
    const int m0 = blockIdx.y * 128, e0 = blockIdx.x * 128;

    const int grp = tid & 7;
    const __half *pA[4], *pB[4];
    uint32_t soff[4];
#pragma unroll
    for (int i = 0; i < 4; i++) {
        int r = (tid >> 3) + i * 32;
        int m = m0 + r;
        int b = m >> 12, t = m & 4095;
        int ts = (t + SHIFTN) & 4095;
        pA[i] = g_xf + ((size_t)((b << 12) + ts)) * DIM + grp * 8;
        pB[i] = g_Wshf + (size_t)(e0 + r) * DIM + grp * 8;
        soff[i] = r * 128 + ((grp ^ (r & 7)) << 4);
    }

    float C[4][4][4];
#pragma unroll
    for (int i = 0; i < 4; i++)
#pragma unroll
        for (int j = 0; j < 4; j++)
#pragma unroll
            for (int q = 0; q < 4; q++) C[i][j][q] = 0.f;

    // prologue: chunks 0,1 into stages 0,1
#pragma unroll
    for (int pc = 0; pc < 2; pc++) {
        uint32_t sb = sbase + pc * G_STAGE;
        int k0 = pc * 64;
#pragma unroll
        for (int i = 0; i < 4; i++) {
            cp16(sb + soff[i], pA[i] + k0);
            cp16(sb + G_B + soff[i], pB[i] + k0);
        }
        cp_commit();
    }

    const int NC = 16;
    int buf = 0;
    for (int c = 0; c < NC; c++) {
        if (c >= NC - 2) cp_wait0(); else cp_wait1();
        __syncthreads();
        if (c + 2 < NC) {
            int nb = buf + 2; if (nb >= G_NST) nb -= G_NST;
            uint32_t sb = sbase + nb * G_STAGE;
            int k0 = (c + 2) * 64;
#pragma unroll
            for (int i = 0; i < 4; i++) {
                cp16(sb + soff[i], pA[i] + k0);
                cp16(sb + G_B + soff[i], pB[i] + k0);
            }
            cp_commit();
        }
        mma_stage_g(sbase + buf * G_STAGE, wm, wn, lane, C);
        if (++buf == G_NST) buf = 0;
    }

#pragma unroll
    for (int i = 0; i < 4; i++)
#pragma unroll
        for (int j = 0; j < 4; j++) {
            int r0 = m0 + wm + i * 16 + (lane >> 2);
            int col = e0 + wn + j * 8 + (lane & 3) * 2;
            __half2 h0 = __floats2half2_rn(C[i][j][0], C[i][j][1]);
            __half2 h1 = __floats2half2_rn(C[i][j][2], C[i][j][3]);
            *(__half2*)&g_xsf[(size_t)r0 * DIM + col]       = h0;
            *(__half2*)&g_xsf[(size_t)(r0 + 8) * DIM + col] = h1;
        }
}

// ---------------------------------------------------------------------------
// blend (fp16 inputs) + layernorm -> fp16 xn
// ---------------------------------------------------------------------------
__inline__ __device__ float warp_sum(float v) {
#pragma unroll
    for (int o = 16; o > 0; o >>= 1) v += __shfl_xor_sync(0xffffffffu, v, o);
    return v;
}

union U4h { uint2 u; __half h[4]; __half2 h2[2]; };

__global__ __launch_bounds__(256)
void k_ln(const float* __restrict__ sg,
          const float* __restrict__ lnw, const float* __restrict__ lnb)
{
    int m = blockIdx.x;
    int tid = threadIdx.x;
    size_t off = (size_t)m * DIM + tid * 4;
    U4h xs, xf;
    xs.u = *(const uint2*)(g_xsf + off);
    xf.u = *(const uint2*)(g_xf + off);
    float4 gv = ((const float4*)sg)[tid];
    float g0 = 1.f/(1.f+expf(-gv.x)), g1 = 1.f/(1.f+expf(-gv.y));
    float g2 = 1.f/(1.f+expf(-gv.z)), g3 = 1.f/(1.f+expf(-gv.w));
    float2 s0 = __half22float2(xs.h2[0]), s1 = __half22float2(xs.h2[1]);
    float2 x0 = __half22float2(xf.h2[0]), x1 = __half22float2(xf.h2[1]);
    float4 v;
    v.x = s0.x*g0 + x0.x*(1.f-g0);
    v.y = s0.y*g1 + x0.y*(1.f-g1);
    v.z = s1.x*g2 + x1.x*(1.f-g2);
    v.w = s1.y*g3 + x1.y*(1.f-g3);

    float s  = v.x + v.y + v.z + v.w;
    float ss = fmaf(v.x, v.x, fmaf(v.y, v.y, fmaf(v.z, v.z, v.w * v.w)));
    s = warp_sum(s); ss = warp_sum(ss);
    __shared__ float sh_s[8], sh_ss[8];
    int wid = tid >> 5, lane = tid & 31;
    if (lane == 0) { sh_s[wid] = s; sh_ss[wid] = ss; }
    __syncthreads();
    if (wid == 0) {
        float a = (lane < 8) ? sh_s[lane] : 0.f;
        float b = (lane < 8) ? sh_ss[lane] : 0.f;
        a = warp_sum(a); b = warp_sum(b);
        if (lane == 0) { sh_s[0] = a; sh_ss[0] = b; }
    }
    __syncthreads();
    float mu  = sh_s[0] * (1.f / DIM);
    float var = sh_ss[0] * (1.f / DIM) - mu * mu;
    float rstd = rsqrtf(var + 1e-5f);
    float4 w4 = ((const float4*)lnw)[tid];
    float4 b4 = ((const float4*)lnb)[tid];
    U4h H;
    H.h[0] = __float2half((v.x - mu) * rstd * w4.x + b4.x);
    H.h[1] = __float2half((v.y - mu) * rstd * w4.y + b4.y);
    H.h[2] = __float2half((v.z - mu) * rstd * w4.z + b4.z);
    H.h[3] = __float2half((v.w - mu) * rstd * w4.w + b4.w);
    *(uint2*)(g_xnf + off) = H.u;
}

// ---------------------------------------------------------------------------
// GEMM 2: [k|v] interleaved = xn @ Wkv^T (plain fp16), fused wkv epilogue
// ---------------------------------------------------------------------------
__global__ __launch_bounds__(256, 2)
void k_gemm_kv(const float* __restrict__ time_first)
{
    extern __shared__ __align__(128) char smc[];
    const uint32_t sbase = smem_u32(smc);
    const int tid = threadIdx.x;
    const int warp = tid >> 5, lane = tid & 31;
    const int wm = (warp & 1) * 64, wn = (warp >> 1) * 32;
    const int m0 = blockIdx.y * 128;

    const int grp = tid & 7;
    const __half *pA[4], *pB[4];
    uint32_t soff[4];
#pragma unroll
    for (int i = 0; i < 4; i++) {
        int r = (tid >> 3) + i * 32;
        pA[i] = g_xnf + (size_t)(m0 + r) * DIM + grp * 8;
        pB[i] = g_Wkvf + (size_t)r * DIM + grp * 8;
        soff[i] = r * 128 + ((grp ^ (r & 7)) << 4);
    }

    float C[4][4][4];
#pragma unroll
    for (int i = 0; i < 4; i++)
#pragma unroll
        for (int j = 0; j < 4; j++)
#pragma unroll
            for (int q = 0; q < 4; q++) C[i][j][q] = 0.f;

#pragma unroll
    for (int pc = 0; pc < 2; pc++) {
        uint32_t sb = sbase + pc * G_STAGE;
        int k0 = pc * 64;
#pragma unroll
        for (int i = 0; i < 4; i++) {
            cp16(sb + soff[i], pA[i] + k0);
            cp16(sb + G_B + soff[i], pB[i] + k0);
        }
        cp_commit();
    }

    const int NC = 16;
    int buf = 0;
    for (int c = 0; c < NC; c++) {
        if (c >= NC - 2) cp_wait0(); else cp_wait1();
        __syncthreads();
        if (c + 2 < NC) {
            int nb = buf + 2; if (nb >= G_NST) nb -= G_NST;
            uint32_t sb = sbase + nb * G_STAGE;
            int k0 = (c + 2) * 64;
#pragma unroll
            for (int i = 0; i < 4; i++) {
                cp16(sb + soff[i], pA[i] + k0);
                cp16(sb + G_B + soff[i], pB[i] + k0);
            }
            cp_commit();
        }
        mma_stage_g(sbase + buf * G_STAGE, wm, wn, lane, C);
        if (++buf == G_NST) buf = 0;
    }

    // C cols: even = k_s, odd = v_s
#pragma unroll
    for (int i = 0; i < 4; i++)
#pragma unroll
        for (int j = 0; j < 4; j++) {
            int r0 = m0 + wm + i * 16 + (lane >> 2);
            int sidx = (wn >> 1) + j * 4 + (lane & 3);
            float ex = expf(time_first[sidx]);
            float k0v = C[i][j][0], v0v = C[i][j][1];
            float k1v = C[i][j][2], v1v = C[i][j][3];
            float w0 = expf(-ex * (1.f / (1.f + expf(-k0v)))) * v0v;
            float w1 = expf(-ex * (1.f / (1.f + expf(-k1v)))) * v1v;
            g_wkv[(size_t)r0 * SDIM + sidx]       = w0;
            g_wkv[(size_t)(r0 + 8) * SDIM + sidx] = w1;
        }
}

// ---------------------------------------------------------------------------
// Recurrence (chunked scan, CH=128)
// ---------------------------------------------------------------------------
__global__ void k_rec_lasts(const float* __restrict__ td)
{
    int ch = blockIdx.x, b = blockIdx.y, s = threadIdx.x;
    float w = expf(td[s]);
    const float* wp = g_wkv + ((size_t)(b * SEQ + ch * CH)) * SDIM + s;
    float st = 0.f;
#pragma unroll 8
    for (int t = 0; t < CH; t++) st = fmaf(st, w, wp[(size_t)t * SDIM]);
    g_lasts[(b * NCH + ch) * SDIM + s] = st;
}

__global__ void k_rec_carry(const float* __restrict__ td, float* __restrict__ last_out)
{
    int b = blockIdx.x, s = threadIdx.x;
    float wC = expf((float)CH * td[s]);
    float st = 0.f;
    for (int c = 0; c < NCH; c++) {
        g_carry[(b * NCH + c) * SDIM + s] = st;
        st = st * wC + g_lasts[(b * NCH + c) * SDIM + s];
    }
    last_out[b * SDIM + s] = st;
}

__global__ void k_rec_scan(const float* __restrict__ td)
{
    int ch = blockIdx.x, b = blockIdx.y, s = threadIdx.x;
    float w = expf(td[s]);
    float st = g_carry[(b * NCH + ch) * SDIM + s];
    size_t m0 = (size_t)(b * SEQ + ch * CH);
    const float* wp = g_wkv + m0 * SDIM + s;
#pragma unroll 8
    for (int t = 0; t < CH; t++) {
        st = fmaf(st, w, wp[(size_t)t * SDIM]);
        g_stf[(m0 + t) * SDIM + s] = __float2half(st);
    }
}

// ---------------------------------------------------------------------------
// GEMM 3: out = states @ Wo^T  (plain fp16, K = 64, CTA 128x256)
// ---------------------------------------------------------------------------
__global__ __launch_bounds__(256)
void k_gemm_out(float* __restrict__ out)
{
    extern __shared__ __align__(128) char smc[];
    const uint32_t sbase = smem_u32(smc);
    const int tid = threadIdx.x;
    const int warp = tid >> 5, lane = tid & 31;
    const int wm = (warp & 1) * 64, wn = (warp >> 1) * 64;
    const int m0 = blockIdx.y * 128, d0 = blockIdx.x * 256;

    const int grp = tid & 7;
#pragma unroll
    for (int i = 0; i < 4; i++) {
        int r = (tid >> 3) + i * 32;
        uint32_t so = r * 128 + ((grp ^ (r & 7)) << 4);
        cp16(sbase + so, g_stf + (size_t)(m0 + r) * SDIM + grp * 8);
    }
#pragma unroll
    for (int i = 0; i < 8; i++) {
        int r = (tid >> 3) + i * 32;     /* 0..255 */
        uint32_t so = r * 128 + ((grp ^ (r & 7)) << 4);
        cp16(sbase + O_B + so, g_Wof + (size_t)(d0 + r) * SDIM + grp * 8);
    }
    cp_commit();

    float C[4][8][4];
#pragma unroll
    for (int i = 0; i < 4; i++)
#pragma unroll
        for (int j = 0; j < 8; j++)
#pragma unroll
            for (int q = 0; q < 4; q++) C[i][j][q] = 0.f;

    cp_wait0();
    __syncthreads();
    mma_stage_o(sbase, wm, wn, lane, C);

#pragma unroll
    for (int i = 0; i < 4; i++)
#pragma unroll
        for (int j = 0; j < 8; j++) {
            int r0 = m0 + wm + i * 16 + (lane >> 2);
            int col = d0 + wn + j * 8 + (lane & 3) * 2;
            *(float2*)&out[(size_t)r0 * DIM + col] =
                make_float2(C[i][j][0], C[i][j][1]);
            *(float2*)&out[(size_t)(r0 + 8) * DIM + col] =
                make_float2(C[i][j][2], C[i][j][3]);
        }
}

// ---------------------------------------------------------------------------
extern "C" void kernel_launch(void* const* d_in, const int* in_sizes, int n_in,
                              void* d_out, int out_size)
{
    const float* x   = (const float*)d_in[0];
    const float* td  = (const float*)d_in[1];
    const float* tf  = (const float*)d_in[2];
    const float* Wk  = (const float*)d_in[3];
    const float* Wv  = (const float*)d_in[4];
    const float* Wo  = (const float*)d_in[5];
    const float* Wsh = (const float*)d_in[6];
    const float* sg  = (const float*)d_in[7];
    const float* lnw = (const float*)d_in[8];
    const float* lnb = (const float*)d_in[9];

    float* out  = (float*)d_out;
    float* last = out + (size_t)MTOT * DIM;

    const int SMEM_G = G_NST * G_STAGE;   // 98304 -> 2 CTA/SM
    const int SMEM_O = 49152;             // A 16K + B 32K
    cudaFuncSetAttribute(k_gemm_shift, cudaFuncAttributeMaxDynamicSharedMemorySize, SMEM_G);
    cudaFuncSetAttribute(k_gemm_kv,    cudaFuncAttributeMaxDynamicSharedMemorySize, SMEM_G);
    cudaFuncSetAttribute(k_gemm_out,   cudaFuncAttributeMaxDynamicSharedMemorySize, SMEM_O);

    k_prep_all<<<16992, 256>>>(x, Wsh, Wk, Wv, Wo);
    k_gemm_shift<<<dim3(DIM / 128, MTOT / 128), 256, SMEM_G>>>();
    k_ln<<<MTOT, 256>>>(sg, lnw, lnb);
    k_gemm_kv<<<dim3(1, MTOT / 128), 256, SMEM_G>>>(tf);   // launch index 3 -> profiled

    k_rec_lasts<<<dim3(NCH, BATCH), SDIM>>>(td);
    k_rec_carry<<<BATCH, SDIM>>>(td, last);
    k_rec_scan <<<dim3(NCH, BATCH), SDIM>>>(td);

    k_gemm_out<<<dim3(DIM / 256, MTOT / 128), 256, SMEM_O>>>(out);
}

// round 16
// speedup vs baseline: 1.0371x; 1.0281x over previous
#include <cuda_runtime.h>
#include <cuda_bf16.h>
#include <cuda_fp16.h>
#include <math.h>
#include <stdint.h>

#define BATCH  8
#define SEQ    4096
#define DIM    1024
#define SDIM   64
#define SHIFTN 2048
#define MTOT   (BATCH*SEQ)   /* 32768 */
#define CH     128
#define NCH    (SEQ/CH)      /* 32 */

/* fp16 GEMMs: CTA 128x128, stage = A 16K + B 16K = 32K, 3 stages, 2 CTA/SM */
#define G_B     16384
#define G_STAGE 32768
#define G_NST   3

// ---------------------------------------------------------------------------
// Device scratch
// ---------------------------------------------------------------------------
__device__ __align__(16) __half g_xsf[(size_t)MTOT * DIM];    /* shift-GEMM out, fp16 */
__device__ __align__(16) __half g_xf[(size_t)MTOT * DIM];     /* x fp16 row-major */
__device__ __align__(16) __half g_Wshf[(size_t)DIM * DIM];    /* W_shift fp16 */
__device__ __align__(16) __half g_xnf[(size_t)MTOT * DIM];    /* xn fp16 */
__device__ __align__(16) __half g_Wkvf[128 * DIM];            /* interleaved k/v fp16 */
__device__ __align__(16) __half g_Wof[DIM * SDIM];            /* W_output fp16 */
__device__ __align__(16) __half g_stf[(size_t)MTOT * SDIM];   /* states fp16 */
__device__ float g_wkv[(size_t)MTOT * SDIM];
__device__ float g_lasts[BATCH * NCH * SDIM];
__device__ float g_carry[BATCH * NCH * SDIM];

// ---------------------------------------------------------------------------
// PTX helpers (sm_80-level portable PTX only)
// ---------------------------------------------------------------------------
__device__ __forceinline__ uint32_t smem_u32(const void* p) {
    uint32_t a;
    asm("{ .reg .u64 t; cvta.to.shared.u64 t, %1; cvt.u32.u64 %0, t; }"
        : "=r"(a) : "l"(p));
    return a;
}
__device__ __forceinline__ void cp16(uint32_t d, const void* s) {
    asm volatile("cp.async.cg.shared.global [%0], [%1], 16;" :: "r"(d), "l"(s));
}
__device__ __forceinline__ void cp_commit() { asm volatile("cp.async.commit_group;"); }
__device__ __forceinline__ void cp_wait0()  { asm volatile("cp.async.wait_group 0;"); }
__device__ __forceinline__ void cp_wait1()  { asm volatile("cp.async.wait_group 1;"); }

__device__ __forceinline__ void ldsm4(uint32_t* r, uint32_t a) {
    asm volatile("ldmatrix.sync.aligned.m8n8.x4.shared.b16 {%0,%1,%2,%3}, [%4];"
                 : "=r"(r[0]), "=r"(r[1]), "=r"(r[2]), "=r"(r[3]) : "r"(a));
}
__device__ __forceinline__ void mma_fp(float* c, const uint32_t* a, const uint32_t* b) {
    asm volatile(
        "mma.sync.aligned.m16n8k16.row.col.f32.f16.f16.f32 "
        "{%0,%1,%2,%3}, {%4,%5,%6,%7}, {%8,%9}, {%0,%1,%2,%3};"
        : "+f"(c[0]), "+f"(c[1]), "+f"(c[2]), "+f"(c[3])
        : "r"(a[0]), "r"(a[1]), "r"(a[2]), "r"(a[3]), "r"(b[0]), "r"(b[1]));
}

// plain fp16 chunk: warp tile 64x32 (4m x 4n); A at base, B at +G_B
__device__ __forceinline__ void mma_stage_g(uint32_t base, int wm, int wn, int lane,
                                            float C[4][4][4])
{
    const int ra = lane & 15;
    const int ha = lane >> 4;
    const int gq = lane >> 3;
    const int rb = ((gq >> 1) * 8) + (lane & 7);
    const int hb = gq & 1;
#pragma unroll
    for (int s = 0; s < 4; s++) {
        uint32_t aa[4][4], bb[2][4];
        const int ca = 2 * s + ha;
        const int cb = 2 * s + hb;
#pragma unroll
        for (int i = 0; i < 4; i++) {
            int r = wm + i * 16 + ra;
            ldsm4(aa[i], base + r * 128 + ((ca ^ (r & 7)) << 4));
        }
#pragma unroll
        for (int p = 0; p < 2; p++) {
            int n = wn + p * 16 + rb;
            ldsm4(bb[p], base + G_B + n * 128 + ((cb ^ (n & 7)) << 4));
        }
#pragma unroll
        for (int i = 0; i < 4; i++)
#pragma unroll
            for (int j = 0; j < 4; j++) {
                const uint32_t* B = &bb[j >> 1][(j & 1) * 2];
                mma_fp(C[i][j], aa[i], B);
            }
    }
}

// ---------------------------------------------------------------------------
// Unified prep kernel (fp32 -> fp16), block-range dispatch
// ---------------------------------------------------------------------------
union U8h { uint4 u; __half h[8]; };

__global__ void k_prep_all(const float* __restrict__ x, const float* __restrict__ Wsh,
                           const float* __restrict__ Wk, const float* __restrict__ Wv,
                           const float* __restrict__ Wo)
{
    int b = blockIdx.x;
    const float* src;
    __half* dst;
    size_t i;
    if (b < 16384) {
        i = ((size_t)b * 256 + threadIdx.x) * 8;
        src = x + i; dst = g_xf + i;
    } else if (b < 16896) {
        i = ((size_t)(b - 16384) * 256 + threadIdx.x) * 8;
        src = Wsh + i; dst = g_Wshf + i;
    } else if (b < 16960) {
        i = ((size_t)(b - 16896) * 256 + threadIdx.x) * 8;
        int row = (int)(i >> 10), col = (int)(i & 1023);
        src = ((row & 1) ? Wv : Wk) + (size_t)(row >> 1) * DIM + col;
        dst = g_Wkvf + i;
    } else {
        i = ((size_t)(b - 16960) * 256 + threadIdx.x) * 8;
        src = Wo + i; dst = g_Wof + i;
    }
    float f[8];
    *(float4*)(f)     = *(const float4*)(src);
    *(float4*)(f + 4) = *(const float4*)(src + 4);
    U8h H;
#pragma unroll
    for (int j = 0; j < 8; j++) H.h[j] = __float2half(f[j]);
    *(uint4*)dst = H.u;
}

// ---------------------------------------------------------------------------
// GEMM 1: g_xsf[m, e] = fp16( x_cat[m, :] @ W_shift[e, :] )
// plain fp16, CTA 128x128, 3-stage (prefetch distance 2), 2 CTA/SM
// ---------------------------------------------------------------------------
__global__ __launch_bounds__(256, 2)
void k_gemm_shift()
{
    extern __shared__ __align__(128) char smc[];
    const uint32_t sbase = smem_u32(smc);
    const int tid = threadIdx.x;
    const int warp = tid >> 5, lane = tid & 31;
    const int wm = (warp & 1) * 64, wn = (warp >> 1) * 32;
    const int m0 = blockIdx.y * 128, e0 = blockIdx.x * 128;

    const int grp = tid & 7;
    const __half *pA[4], *pB[4];
    uint32_t soff[4];
#pragma unroll
    for (int i = 0; i < 4; i++) {
        int r = (tid >> 3) + i * 32;
        int m = m0 + r;
        int b = m >> 12, t = m & 4095;
        int ts = (t + SHIFTN) & 4095;
        pA[i] = g_xf + ((size_t)((b << 12) + ts)) * DIM + grp * 8;
        pB[i] = g_Wshf + (size_t)(e0 + r) * DIM + grp * 8;
        soff[i] = r * 128 + ((grp ^ (r & 7)) << 4);
    }

    float C[4][4][4];
#pragma unroll
    for (int i = 0; i < 4; i++)
#pragma unroll
        for (int j = 0; j < 4; j++)
#pragma unroll
            for (int q = 0; q < 4; q++) C[i][j][q] = 0.f;

    // prologue: chunks 0,1 into stages 0,1
#pragma unroll
    for (int pc = 0; pc < 2; pc++) {
        uint32_t sb = sbase + pc * G_STAGE;
        int k0 = pc * 64;
#pragma unroll
        for (int i = 0; i < 4; i++) {
            cp16(sb + soff[i], pA[i] + k0);
            cp16(sb + G_B + soff[i], pB[i] + k0);
        }
        cp_commit();
    }

    const int NC = 16;
    int buf = 0;
    for (int c = 0; c < NC; c++) {
        if (c >= NC - 2) cp_wait0(); else cp_wait1();
        __syncthreads();
        if (c + 2 < NC) {
            int nb = buf + 2; if (nb >= G_NST) nb -= G_NST;
            uint32_t sb = sbase + nb * G_STAGE;
            int k0 = (c + 2) * 64;
#pragma unroll
            for (int i = 0; i < 4; i++) {
                cp16(sb + soff[i], pA[i] + k0);
                cp16(sb + G_B + soff[i], pB[i] + k0);
            }
            cp_commit();
        }
        mma_stage_g(sbase + buf * G_STAGE, wm, wn, lane, C);
        if (++buf == G_NST) buf = 0;
    }

#pragma unroll
    for (int i = 0; i < 4; i++)
#pragma unroll
        for (int j = 0; j < 4; j++) {
            int r0 = m0 + wm + i * 16 + (lane >> 2);
            int col = e0 + wn + j * 8 + (lane & 3) * 2;
            __half2 h0 = __floats2half2_rn(C[i][j][0], C[i][j][1]);
            __half2 h1 = __floats2half2_rn(C[i][j][2], C[i][j][3]);
            *(__half2*)&g_xsf[(size_t)r0 * DIM + col]       = h0;
            *(__half2*)&g_xsf[(size_t)(r0 + 8) * DIM + col] = h1;
        }
}

// ---------------------------------------------------------------------------
// blend (fp16 inputs) + layernorm -> fp16 xn
// ---------------------------------------------------------------------------
__inline__ __device__ float warp_sum(float v) {
#pragma unroll
    for (int o = 16; o > 0; o >>= 1) v += __shfl_xor_sync(0xffffffffu, v, o);
    return v;
}

union U4h { uint2 u; __half h[4]; __half2 h2[2]; };

__global__ __launch_bounds__(256)
void k_ln(const float* __restrict__ sg,
          const float* __restrict__ lnw, const float* __restrict__ lnb)
{
    int m = blockIdx.x;
    int tid = threadIdx.x;
    size_t off = (size_t)m * DIM + tid * 4;
    U4h xs, xf;
    xs.u = *(const uint2*)(g_xsf + off);
    xf.u = *(const uint2*)(g_xf + off);
    float4 gv = ((const float4*)sg)[tid];
    float g0 = 1.f/(1.f+expf(-gv.x)), g1 = 1.f/(1.f+expf(-gv.y));
    float g2 = 1.f/(1.f+expf(-gv.z)), g3 = 1.f/(1.f+expf(-gv.w));
    float2 s0 = __half22float2(xs.h2[0]), s1 = __half22float2(xs.h2[1]);
    float2 x0 = __half22float2(xf.h2[0]), x1 = __half22float2(xf.h2[1]);
    float4 v;
    v.x = s0.x*g0 + x0.x*(1.f-g0);
    v.y = s0.y*g1 + x0.y*(1.f-g1);
    v.z = s1.x*g2 + x1.x*(1.f-g2);
    v.w = s1.y*g3 + x1.y*(1.f-g3);

    float s  = v.x + v.y + v.z + v.w;
    float ss = fmaf(v.x, v.x, fmaf(v.y, v.y, fmaf(v.z, v.z, v.w * v.w)));
    s = warp_sum(s); ss = warp_sum(ss);
    __shared__ float sh_s[8], sh_ss[8];
    int wid = tid >> 5, lane = tid & 31;
    if (lane == 0) { sh_s[wid] = s; sh_ss[wid] = ss; }
    __syncthreads();
    if (wid == 0) {
        float a = (lane < 8) ? sh_s[lane] : 0.f;
        float b = (lane < 8) ? sh_ss[lane] : 0.f;
        a = warp_sum(a); b = warp_sum(b);
        if (lane == 0) { sh_s[0] = a; sh_ss[0] = b; }
    }
    __syncthreads();
    float mu  = sh_s[0] * (1.f / DIM);
    float var = sh_ss[0] * (1.f / DIM) - mu * mu;
    float rstd = rsqrtf(var + 1e-5f);
    float4 w4 = ((const float4*)lnw)[tid];
    float4 b4 = ((const float4*)lnb)[tid];
    U4h H;
    H.h[0] = __float2half((v.x - mu) * rstd * w4.x + b4.x);
    H.h[1] = __float2half((v.y - mu) * rstd * w4.y + b4.y);
    H.h[2] = __float2half((v.z - mu) * rstd * w4.z + b4.z);
    H.h[3] = __float2half((v.w - mu) * rstd * w4.w + b4.w);
    *(uint2*)(g_xnf + off) = H.u;
}

// ---------------------------------------------------------------------------
// GEMM 2: [k|v] interleaved = xn @ Wkv^T (plain fp16), fused wkv epilogue
// ---------------------------------------------------------------------------
__global__ __launch_bounds__(256, 2)
void k_gemm_kv(const float* __restrict__ time_first)
{
    extern __shared__ __align__(128) char smc[];
    const uint32_t sbase = smem_u32(smc);
    const int tid = threadIdx.x;
    const int warp = tid >> 5, lane = tid & 31;
    const int wm = (warp & 1) * 64, wn = (warp >> 1) * 32;
    const int m0 = blockIdx.y * 128;

    const int grp = tid & 7;
    const __half *pA[4], *pB[4];
    uint32_t soff[4];
#pragma unroll
    for (int i = 0; i < 4; i++) {
        int r = (tid >> 3) + i * 32;
        pA[i] = g_xnf + (size_t)(m0 + r) * DIM + grp * 8;
        pB[i] = g_Wkvf + (size_t)r * DIM + grp * 8;
        soff[i] = r * 128 + ((grp ^ (r & 7)) << 4);
    }

    float C[4][4][4];
#pragma unroll
    for (int i = 0; i < 4; i++)
#pragma unroll
        for (int j = 0; j < 4; j++)
#pragma unroll
            for (int q = 0; q < 4; q++) C[i][j][q] = 0.f;

#pragma unroll
    for (int pc = 0; pc < 2; pc++) {
        uint32_t sb = sbase + pc * G_STAGE;
        int k0 = pc * 64;
#pragma unroll
        for (int i = 0; i < 4; i++) {
            cp16(sb + soff[i], pA[i] + k0);
            cp16(sb + G_B + soff[i], pB[i] + k0);
        }
        cp_commit();
    }

    const int NC = 16;
    int buf = 0;
    for (int c = 0; c < NC; c++) {
        if (c >= NC - 2) cp_wait0(); else cp_wait1();
        __syncthreads();
        if (c + 2 < NC) {
            int nb = buf + 2; if (nb >= G_NST) nb -= G_NST;
            uint32_t sb = sbase + nb * G_STAGE;
            int k0 = (c + 2) * 64;
#pragma unroll
            for (int i = 0; i < 4; i++) {
                cp16(sb + soff[i], pA[i] + k0);
                cp16(sb + G_B + soff[i], pB[i] + k0);
            }
            cp_commit();
        }
        mma_stage_g(sbase + buf * G_STAGE, wm, wn, lane, C);
        if (++buf == G_NST) buf = 0;
    }

    // C cols: even = k_s, odd = v_s
#pragma unroll
    for (int i = 0; i < 4; i++)
#pragma unroll
        for (int j = 0; j < 4; j++) {
            int r0 = m0 + wm + i * 16 + (lane >> 2);
            int sidx = (wn >> 1) + j * 4 + (lane & 3);
            float ex = expf(time_first[sidx]);
            float k0v = C[i][j][0], v0v = C[i][j][1];
            float k1v = C[i][j][2], v1v = C[i][j][3];
            float w0 = expf(-ex * (1.f / (1.f + expf(-k0v)))) * v0v;
            float w1 = expf(-ex * (1.f / (1.f + expf(-k1v)))) * v1v;
            g_wkv[(size_t)r0 * SDIM + sidx]       = w0;
            g_wkv[(size_t)(r0 + 8) * SDIM + sidx] = w1;
        }
}

// ---------------------------------------------------------------------------
// Recurrence (chunked scan, CH=128)
// ---------------------------------------------------------------------------
__global__ void k_rec_lasts(const float* __restrict__ td)
{
    int ch = blockIdx.x, b = blockIdx.y, s = threadIdx.x;
    float w = expf(td[s]);
    const float* wp = g_wkv + ((size_t)(b * SEQ + ch * CH)) * SDIM + s;
    float st = 0.f;
#pragma unroll 8
    for (int t = 0; t < CH; t++) st = fmaf(st, w, wp[(size_t)t * SDIM]);
    g_lasts[(b * NCH + ch) * SDIM + s] = st;
}

__global__ void k_rec_carry(const float* __restrict__ td, float* __restrict__ last_out)
{
    int b = blockIdx.x, s = threadIdx.x;
    float wC = expf((float)CH * td[s]);
    float st = 0.f;
    for (int c = 0; c < NCH; c++) {
        g_carry[(b * NCH + c) * SDIM + s] = st;
        st = st * wC + g_lasts[(b * NCH + c) * SDIM + s];
    }
    last_out[b * SDIM + s] = st;
}

__global__ void k_rec_scan(const float* __restrict__ td)
{
    int ch = blockIdx.x, b = blockIdx.y, s = threadIdx.x;
    float w = expf(td[s]);
    float st = g_carry[(b * NCH + ch) * SDIM + s];
    size_t m0 = (size_t)(b * SEQ + ch * CH);
    const float* wp = g_wkv + m0 * SDIM + s;
#pragma unroll 8
    for (int t = 0; t < CH; t++) {
        st = fmaf(st, w, wp[(size_t)t * SDIM]);
        g_stf[(m0 + t) * SDIM + s] = __float2half(st);
    }
}

// ---------------------------------------------------------------------------
// GEMM 3: out = states @ Wo^T  (plain fp16, K = 64, single chunk, CTA 128x128)
// ---------------------------------------------------------------------------
__global__ __launch_bounds__(256)
void k_gemm_out(float* __restrict__ out)
{
    extern __shared__ __align__(128) char smc[];
    const uint32_t sbase = smem_u32(smc);
    const int tid = threadIdx.x;
    const int warp = tid >> 5, lane = tid & 31;
    const int wm = (warp & 1) * 64, wn = (warp >> 1) * 32;
    const int m0 = blockIdx.y * 128, d0 = blockIdx.x * 128;

    const int grp = tid & 7;
#pragma unroll
    for (int i = 0; i < 4; i++) {
        int r = (tid >> 3) + i * 32;
        uint32_t so = r * 128 + ((grp ^ (r & 7)) << 4);
        cp16(sbase + so,       g_stf + (size_t)(m0 + r) * SDIM + grp * 8);
        cp16(sbase + G_B + so, g_Wof + (size_t)(d0 + r) * SDIM + grp * 8);
    }
    cp_commit();

    float C[4][4][4];
#pragma unroll
    for (int i = 0; i < 4; i++)
#pragma unroll
        for (int j = 0; j < 4; j++)
#pragma unroll
            for (int q = 0; q < 4; q++) C[i][j][q] = 0.f;

    cp_wait0();
    __syncthreads();
    mma_stage_g(sbase, wm, wn, lane, C);

#pragma unroll
    for (int i = 0; i < 4; i++)
#pragma unroll
        for (int j = 0; j < 4; j++) {
            int r0 = m0 + wm + i * 16 + (lane >> 2);
            int col = d0 + wn + j * 8 + (lane & 3) * 2;
            *(float2*)&out[(size_t)r0 * DIM + col] =
                make_float2(C[i][j][0], C[i][j][1]);
            *(float2*)&out[(size_t)(r0 + 8) * DIM + col] =
                make_float2(C[i][j][2], C[i][j][3]);
        }
}

// ---------------------------------------------------------------------------
extern "C" void kernel_launch(void* const* d_in, const int* in_sizes, int n_in,
                              void* d_out, int out_size)
{
    const float* x   = (const float*)d_in[0];
    const float* td  = (const float*)d_in[1];
    const float* tf  = (const float*)d_in[2];
    const float* Wk  = (const float*)d_in[3];
    const float* Wv  = (const float*)d_in[4];
    const float* Wo  = (const float*)d_in[5];
    const float* Wsh = (const float*)d_in[6];
    const float* sg  = (const float*)d_in[7];
    const float* lnw = (const float*)d_in[8];
    const float* lnb = (const float*)d_in[9];

    float* out  = (float*)d_out;
    float* last = out + (size_t)MTOT * DIM;

    const int SMEM_G = G_NST * G_STAGE;   // 98304 -> 2 CTA/SM
    const int SMEM_O = G_STAGE;           // 32768
    cudaFuncSetAttribute(k_gemm_shift, cudaFuncAttributeMaxDynamicSharedMemorySize, SMEM_G);
    cudaFuncSetAttribute(k_gemm_kv,    cudaFuncAttributeMaxDynamicSharedMemorySize, SMEM_G);
    cudaFuncSetAttribute(k_gemm_out,   cudaFuncAttributeMaxDynamicSharedMemorySize, SMEM_O);

    k_prep_all<<<16992, 256>>>(x, Wsh, Wk, Wv, Wo);
    k_gemm_shift<<<dim3(DIM / 128, MTOT / 128), 256, SMEM_G>>>();
    k_ln<<<MTOT, 256>>>(sg, lnw, lnb);
    k_gemm_kv<<<dim3(1, MTOT / 128), 256, SMEM_G>>>(tf);   // launch index 3 -> profiled

    k_rec_lasts<<<dim3(NCH, BATCH), SDIM>>>(td);
    k_rec_carry<<<BATCH, SDIM>>>(td, last);
    k_rec_scan <<<dim3(NCH, BATCH), SDIM>>>(td);

    k_gemm_out<<<dim3(DIM / 128, MTOT / 128), 256, SMEM_O>>>(out);
}